// round 2
// baseline (speedup 1.0000x reference)
#include <cuda_runtime.h>
#include <cuda_bf16.h>
#include <math_constants.h>
#include <cstdint>

#define BB    64
#define TT    2048
#define DRNN  1024
#define DEMB  512
#define DATT  128
#define NF    32
#define KS    31
#define PADW  15

// ---------------- device scratch (no allocations allowed) ----------------
__device__ float  g_pq[BB * DATT];          // processed query [B][128]
__device__ float2 g_wd2[64 * 32];           // Wd packed: [p][f] = (Wd[2p][f], Wd[2p+1][f])
__device__ float2 g_cw2[62 * 16];           // conv_w packed: [c*31+k][fp] = (cw[2fp][c][k], cw[2fp+1][c][k])
__device__ float  g_energy[BB * TT];        // raw energies (pre-mask)
__device__ float  g_ctx_part[8 * BB * DEMB];// context partial sums per t-split

// ---------------- helpers ----------------
__device__ __forceinline__ float2 ffma2(float2 a, float2 b, float2 c) {
    float2 d;
    asm("{\n\t"
        ".reg .b64 ra, rb, rc, rd;\n\t"
        "mov.b64 ra, {%2,%3};\n\t"
        "mov.b64 rb, {%4,%5};\n\t"
        "mov.b64 rc, {%6,%7};\n\t"
        "fma.rn.f32x2 rd, ra, rb, rc;\n\t"
        "mov.b64 {%0,%1}, rd;\n\t"
        "}"
        : "=f"(d.x), "=f"(d.y)
        : "f"(a.x), "f"(a.y), "f"(b.x), "f"(b.y), "f"(c.x), "f"(c.y));
    return d;
}

__device__ __forceinline__ float tanh_fast(float x) {
    float y;
    asm("tanh.approx.f32 %0, %1;" : "=f"(y) : "f"(x));
    return y;
}

// ---------------- K0: pq GEMM + weight repacking ----------------
__global__ __launch_bounds__(128) void prep_kernel(
    const float* __restrict__ hidden, const float* __restrict__ Wq,
    const float* __restrict__ convw,  const float* __restrict__ Wd)
{
    __shared__ float s_h[DRNN];
    int tid = threadIdx.x, b = blockIdx.x;
    for (int i = tid; i < DRNN; i += 128) s_h[i] = hidden[(size_t)b * DRNN + i];
    __syncthreads();

    int w = tid >> 5, lane = tid & 31;
    for (int a = w; a < DATT; a += 4) {
        const float* wq = Wq + (size_t)a * DRNN;
        float acc = 0.f;
        #pragma unroll 8
        for (int k = lane; k < DRNN; k += 32) acc = fmaf(s_h[k], wq[k], acc);
        #pragma unroll
        for (int off = 16; off; off >>= 1) acc += __shfl_down_sync(0xffffffffu, acc, off);
        if (lane == 0) g_pq[b * DATT + a] = acc;
    }

    if (b == 0) {
        // Wd: [a][f] row-major, a<128, f<32  ->  g_wd2[p*32+f]
        for (int i = tid; i < 64 * 32; i += 128) {
            int p = i >> 5, f = i & 31;
            g_wd2[i] = make_float2(Wd[(2 * p) * NF + f], Wd[(2 * p + 1) * NF + f]);
        }
        // conv_w: [f][c][k] row-major (f<32, c<2, k<31) -> g_cw2[ck*16+fp]
        for (int i = tid; i < 62 * 16; i += 128) {
            int ck = i >> 4, fp = i & 15;
            g_cw2[i] = make_float2(convw[(2 * fp) * 62 + ck], convw[(2 * fp + 1) * 62 + ck]);
        }
    }
}

// ---------------- K1: conv + paw + tanh + v-dot -> energies ----------------
// grid (16, 64): 128 t per block, one batch per blockIdx.y. 128 threads.
#define K1_SMEM_FLOATS 15136
#define K1_SMEM_BYTES  (K1_SMEM_FLOATS * 4)

__global__ __launch_bounds__(128) void energy_kernel(
    const float* __restrict__ pm, const float* __restrict__ aw,
    const float* __restrict__ wv)
{
    extern __shared__ float sm[];
    float* s_aw  = sm;            // 2*160
    float* s_cw  = sm + 320;      // 62*16 float2
    float* s_wd  = sm + 2304;     // 64*32 float2
    float* s_loc = sm + 6400;     // 128*33
    float* s_pm  = sm + 10624;    // 32*129
    float* s_pq  = sm + 14752;    // 128
    float* s_wv  = sm + 14880;    // 128
    float* s_ep  = sm + 15008;    // 128

    int tid = threadIdx.x;
    int b   = blockIdx.y;
    int t0  = blockIdx.x * 128;
    int w   = tid >> 5, lane = tid & 31;

    // ---- load shared state ----
    const float* awB = aw + (size_t)b * 2 * TT;
    for (int i = tid; i < 2 * 158; i += 128) {
        int c = i / 158, j = i - c * 158;
        int tg = t0 + j - PADW;
        s_aw[c * 160 + j] = (tg >= 0 && tg < TT) ? awB[(size_t)c * TT + tg] : 0.f;
    }
    {
        const float4* src = (const float4*)g_cw2;   // 496 float4
        float4* dst = (float4*)s_cw;
        for (int i = tid; i < 496; i += 128) dst[i] = src[i];
    }
    {
        const float4* src = (const float4*)g_wd2;   // 1024 float4
        float4* dst = (float4*)s_wd;
        for (int i = tid; i < 1024; i += 128) dst[i] = src[i];
    }
    s_pq[tid] = g_pq[b * DATT + tid];
    s_wv[tid] = wv[tid];
    __syncthreads();

    // ---- conv: thread tid computes loc[t0+tid][f] for all 32 filters ----
    {
        float2 acc[16];
        #pragma unroll
        for (int fp = 0; fp < 16; fp++) acc[fp] = make_float2(0.f, 0.f);
        for (int ck = 0; ck < 62; ck++) {
            int c = (ck >= 31), k = ck - c * 31;
            float av = s_aw[c * 160 + tid + k];
            float2 av2 = make_float2(av, av);
            const float4* row = (const float4*)(s_cw + ck * 32);
            #pragma unroll
            for (int q = 0; q < 8; q++) {
                float4 w4 = row[q];
                acc[2 * q]     = ffma2(av2, make_float2(w4.x, w4.y), acc[2 * q]);
                acc[2 * q + 1] = ffma2(av2, make_float2(w4.z, w4.w), acc[2 * q + 1]);
            }
        }
        #pragma unroll
        for (int fp = 0; fp < 16; fp++) {
            s_loc[tid * 33 + 2 * fp]     = acc[fp].x;
            s_loc[tid * 33 + 2 * fp + 1] = acc[fp].y;
        }
    }
    __syncthreads();

    // ---- energies: 4 groups of 32 t; lane = t, warp w covers a-pairs [w*16, w*16+16) ----
    const int pbase = w * 16;
    for (int g = 0; g < 4; g++) {
        const float* pmB = pm + ((size_t)b * TT + t0 + g * 32) * DATT;
        for (int i = tid; i < 32 * 128; i += 128) {
            int t = i >> 7, a = i & 127;
            s_pm[t * 129 + a] = pmB[i];
        }
        __syncthreads();

        float loc_r[32];
        int tl = g * 32 + lane;
        #pragma unroll
        for (int f = 0; f < 32; f++) loc_r[f] = s_loc[tl * 33 + f];

        float epart = 0.f;
        #pragma unroll 2
        for (int pp = 0; pp < 16; pp++) {
            int p = pbase + pp;
            float2 acc = *(const float2*)(s_pq + 2 * p);
            const float4* wrow = (const float4*)(s_wd + p * 64);
            #pragma unroll
            for (int j = 0; j < 16; j++) {
                float4 w4 = wrow[j];
                float l0 = loc_r[2 * j], l1 = loc_r[2 * j + 1];
                acc = ffma2(make_float2(l0, l0), make_float2(w4.x, w4.y), acc);
                acc = ffma2(make_float2(l1, l1), make_float2(w4.z, w4.w), acc);
            }
            float x0 = acc.x + s_pm[lane * 129 + 2 * p];
            float x1 = acc.y + s_pm[lane * 129 + 2 * p + 1];
            epart = fmaf(s_wv[2 * p],     tanh_fast(x0), epart);
            epart = fmaf(s_wv[2 * p + 1], tanh_fast(x1), epart);
        }
        s_ep[w * 32 + lane] = epart;
        __syncthreads();
        if (tid < 32) {
            float e = s_ep[tid] + s_ep[32 + tid] + s_ep[64 + tid] + s_ep[96 + tid];
            g_energy[(size_t)b * TT + t0 + g * 32 + tid] = e;
        }
        __syncthreads();
    }
}

// ---------------- K2: masked softmax over T per batch ----------------
// FIX R1: mask is int32 (jax bool marshalled as int32 per harness contract),
// NOT bytes. Reading it as bytes was the R1 correctness failure.
__global__ __launch_bounds__(256) void softmax_kernel(
    const int* __restrict__ mask, float* __restrict__ out_w)
{
    __shared__ float red[32];
    int tid = threadIdx.x, b = blockIdx.x;
    float vals[8];
    float mx = -CUDART_INF_F;
    #pragma unroll
    for (int j = 0; j < 8; j++) {
        int t = tid + j * 256;
        float e = g_energy[(size_t)b * TT + t];
        float v = (mask[(size_t)b * TT + t] != 0) ? -CUDART_INF_F : e;
        vals[j] = v;
        mx = fmaxf(mx, v);
    }
    #pragma unroll
    for (int off = 16; off; off >>= 1) mx = fmaxf(mx, __shfl_xor_sync(0xffffffffu, mx, off));
    if ((tid & 31) == 0) red[tid >> 5] = mx;
    __syncthreads();
    if (tid < 32) {
        float m = (tid < 8) ? red[tid] : -CUDART_INF_F;
        #pragma unroll
        for (int off = 4; off; off >>= 1) m = fmaxf(m, __shfl_xor_sync(0xffffffffu, m, off));
        red[tid] = m;
    }
    __syncthreads();
    mx = red[0];

    float s = 0.f;
    #pragma unroll
    for (int j = 0; j < 8; j++) { float ev = __expf(vals[j] - mx); vals[j] = ev; s += ev; }
    #pragma unroll
    for (int off = 16; off; off >>= 1) s += __shfl_xor_sync(0xffffffffu, s, off);
    __syncthreads();
    if ((tid & 31) == 0) red[tid >> 5] = s;
    __syncthreads();
    if (tid < 32) {
        float m = (tid < 8) ? red[tid] : 0.f;
        #pragma unroll
        for (int off = 4; off; off >>= 1) m += __shfl_xor_sync(0xffffffffu, m, off);
        red[tid] = m;
    }
    __syncthreads();
    float inv = 1.f / red[0];
    #pragma unroll
    for (int j = 0; j < 8; j++) out_w[(size_t)b * TT + tid + j * 256] = vals[j] * inv;
}

// ---------------- K3: context partials (HBM-bound, 512 blocks) ----------------
__global__ __launch_bounds__(128) void context_kernel(
    const float* __restrict__ memory, const float* __restrict__ wgt)
{
    __shared__ float s_w[256];
    int tid = threadIdx.x;
    int b = blockIdx.y, ts = blockIdx.x;
    int t0 = ts * 256;
    s_w[tid]       = wgt[(size_t)b * TT + t0 + tid];
    s_w[tid + 128] = wgt[(size_t)b * TT + t0 + tid + 128];
    __syncthreads();

    const float4* m4 = (const float4*)(memory + ((size_t)b * TT + t0) * DEMB) + tid;
    float4 a0 = make_float4(0, 0, 0, 0), a1 = make_float4(0, 0, 0, 0);
    #pragma unroll 4
    for (int i = 0; i < 256; i += 2) {
        float w0 = s_w[i], w1 = s_w[i + 1];
        float4 v0 = m4[(size_t)i * 128];
        float4 v1 = m4[(size_t)(i + 1) * 128];
        a0.x = fmaf(w0, v0.x, a0.x); a0.y = fmaf(w0, v0.y, a0.y);
        a0.z = fmaf(w0, v0.z, a0.z); a0.w = fmaf(w0, v0.w, a0.w);
        a1.x = fmaf(w1, v1.x, a1.x); a1.y = fmaf(w1, v1.y, a1.y);
        a1.z = fmaf(w1, v1.z, a1.z); a1.w = fmaf(w1, v1.w, a1.w);
    }
    float4 r = make_float4(a0.x + a1.x, a0.y + a1.y, a0.z + a1.z, a0.w + a1.w);
    ((float4*)g_ctx_part)[(size_t)ts * (BB * DEMB / 4) + b * (DEMB / 4) + tid] = r;
}

// ---------------- K4: reduce context partials ----------------
__global__ __launch_bounds__(256) void reduce_kernel(float* __restrict__ out_ctx)
{
    int i = blockIdx.x * 256 + threadIdx.x;   // 32768 outputs
    float s = 0.f;
    #pragma unroll
    for (int ts = 0; ts < 8; ts++) s += g_ctx_part[(size_t)ts * BB * DEMB + i];
    out_ctx[i] = s;
}

// ---------------- launch ----------------
extern "C" void kernel_launch(void* const* d_in, const int* in_sizes, int n_in,
                              void* d_out, int out_size)
{
    const float* hidden = (const float*)d_in[0];          // [B, 1024]
    const float* memory = (const float*)d_in[1];          // [B, T, 512]
    const float* pm     = (const float*)d_in[2];          // [B, T, 128]
    const float* awc    = (const float*)d_in[3];          // [B, 2, T]
    const int*   mask   = (const int*)d_in[4];            // [B, T] bool->int32
    const float* Wq     = (const float*)d_in[5];          // [128, 1024]
    const float* Wv     = (const float*)d_in[6];          // [1, 128]
    const float* convw  = (const float*)d_in[7];          // [32, 2, 31]
    const float* Wd     = (const float*)d_in[8];          // [128, 32]

    float* out     = (float*)d_out;
    float* out_ctx = out;                  // [B, 512]
    float* out_w   = out + BB * DEMB;      // [B, T]

    cudaFuncSetAttribute(energy_kernel,
                         cudaFuncAttributeMaxDynamicSharedMemorySize, K1_SMEM_BYTES);

    prep_kernel<<<64, 128>>>(hidden, Wq, convw, Wd);
    energy_kernel<<<dim3(16, 64), 128, K1_SMEM_BYTES>>>(pm, awc, Wv);
    softmax_kernel<<<64, 256>>>(mask, out_w);
    context_kernel<<<dim3(8, 64), 128>>>(memory, out_w);
    reduce_kernel<<<128, 256>>>(out_ctx);
}

// round 3
// speedup vs baseline: 1.0630x; 1.0630x over previous
#include <cuda_runtime.h>
#include <cuda_bf16.h>
#include <math_constants.h>
#include <cstdint>

#define BB    64
#define TT    2048
#define DRNN  1024
#define DEMB  512
#define DATT  128
#define NF    32
#define KS    31
#define PADW  15
#define NSPLIT 16

// ---------------- device scratch ----------------
__device__ float  g_pq[BB * DATT];
__device__ float2 g_wd2[64 * 32];            // [p][f] = (Wd[2p][f], Wd[2p+1][f])
__device__ float2 g_cw2[62 * 16];            // [ck][fp] = (cw[2fp][ck], cw[2fp+1][ck])
__device__ float  g_energy[BB * TT];
__device__ float  g_ctx_part[NSPLIT * BB * DEMB];

typedef unsigned long long ull;

// ---------------- helpers: zero-mov f32x2 ----------------
__device__ __forceinline__ ull ffma2u(ull a, ull b, ull c) {
    ull d;
    asm("fma.rn.f32x2 %0, %1, %2, %3;" : "=l"(d) : "l"(a), "l"(b), "l"(c));
    return d;
}
__device__ __forceinline__ ull pack2(float x, float y) {
    ull r; asm("mov.b64 %0, {%1, %2};" : "=l"(r) : "f"(x), "f"(y)); return r;
}
__device__ __forceinline__ float2 unpack2(ull v) {
    float2 f; asm("mov.b64 {%0, %1}, %2;" : "=f"(f.x), "=f"(f.y) : "l"(v)); return f;
}
__device__ __forceinline__ float tanh_fast(float x) {
    float y; asm("tanh.approx.f32 %0, %1;" : "=f"(y) : "f"(x)); return y;
}

// ---------------- K0: pq GEMM + weight repacking ----------------
__global__ __launch_bounds__(128) void prep_kernel(
    const float* __restrict__ hidden, const float* __restrict__ Wq,
    const float* __restrict__ convw,  const float* __restrict__ Wd)
{
    __shared__ float s_h[DRNN];
    int tid = threadIdx.x, b = blockIdx.x;
    for (int i = tid; i < DRNN; i += 128) s_h[i] = hidden[(size_t)b * DRNN + i];
    __syncthreads();

    int w = tid >> 5, lane = tid & 31;
    for (int a = w; a < DATT; a += 4) {
        const float* wq = Wq + (size_t)a * DRNN;
        float acc = 0.f;
        #pragma unroll 8
        for (int k = lane; k < DRNN; k += 32) acc = fmaf(s_h[k], wq[k], acc);
        #pragma unroll
        for (int off = 16; off; off >>= 1) acc += __shfl_down_sync(0xffffffffu, acc, off);
        if (lane == 0) g_pq[b * DATT + a] = acc;
    }

    if (b == 0) {
        for (int i = tid; i < 64 * 32; i += 128) {
            int p = i >> 5, f = i & 31;
            g_wd2[i] = make_float2(Wd[(2 * p) * NF + f], Wd[(2 * p + 1) * NF + f]);
        }
        for (int i = tid; i < 62 * 16; i += 128) {
            int ck = i >> 4, fp = i & 15;
            g_cw2[i] = make_float2(convw[(2 * fp) * 62 + ck], convw[(2 * fp + 1) * 62 + ck]);
        }
    }
}

// ---------------- K1: conv + paw + tanh + v-dot -> energies ----------------
#define K1_SMEM_FLOATS 15136
#define K1_SMEM_BYTES  (K1_SMEM_FLOATS * 4)

__global__ __launch_bounds__(128) void energy_kernel(
    const float* __restrict__ pm, const float* __restrict__ aw,
    const float* __restrict__ wv)
{
    extern __shared__ float sm[];
    float* s_aw  = sm;            // 2*160
    float* s_cw  = sm + 320;      // 62*16 float2 (16B-aligned: 1280 B)
    float* s_wd  = sm + 2304;     // 64*32 float2 (16B-aligned: 9216 B)
    float* s_loc = sm + 6400;     // 128*33
    float* s_pm  = sm + 10624;    // 32*129
    float* s_pq  = sm + 14752;    // 128 (8B-aligned)
    float* s_wv  = sm + 14880;    // 128
    float* s_ep  = sm + 15008;    // 128

    int tid = threadIdx.x;
    int b   = blockIdx.y;
    int t0  = blockIdx.x * 128;
    int w   = tid >> 5, lane = tid & 31;

    // ---- load shared state ----
    const float* awB = aw + (size_t)b * 2 * TT;
    for (int i = tid; i < 2 * 158; i += 128) {
        int c = i / 158, j = i - c * 158;
        int tg = t0 + j - PADW;
        s_aw[c * 160 + j] = (tg >= 0 && tg < TT) ? awB[(size_t)c * TT + tg] : 0.f;
    }
    {
        const float4* src = (const float4*)g_cw2;
        float4* dst = (float4*)s_cw;
        for (int i = tid; i < 496; i += 128) dst[i] = src[i];
    }
    {
        const float4* src = (const float4*)g_wd2;
        float4* dst = (float4*)s_wd;
        for (int i = tid; i < 1024; i += 128) dst[i] = src[i];
    }
    s_pq[tid] = g_pq[b * DATT + tid];
    s_wv[tid] = wv[tid];
    __syncthreads();

    // ---- conv: thread tid -> loc[t0+tid][all 32 f]; pure LDS.128 + FFMA2 ----
    {
        ull acc[16];
        #pragma unroll
        for (int fp = 0; fp < 16; fp++) acc[fp] = 0ULL;   // (0.f, 0.f)
        #pragma unroll 2
        for (int ck = 0; ck < 62; ck++) {
            int c = (ck >= 31), k = ck - c * 31;
            float av = s_aw[c * 160 + tid + k];
            ull av2 = pack2(av, av);                       // one mov per tap (hoisted)
            const ulonglong2* row = (const ulonglong2*)(s_cw + ck * 32);
            #pragma unroll
            for (int q = 0; q < 8; q++) {
                ulonglong2 w2 = row[q];                    // LDS.128 = two f32 pairs
                acc[2 * q]     = ffma2u(av2, w2.x, acc[2 * q]);
                acc[2 * q + 1] = ffma2u(av2, w2.y, acc[2 * q + 1]);
            }
        }
        #pragma unroll
        for (int fp = 0; fp < 16; fp++) {
            float2 a2 = unpack2(acc[fp]);
            s_loc[tid * 33 + 2 * fp]     = a2.x;
            s_loc[tid * 33 + 2 * fp + 1] = a2.y;
        }
    }
    __syncthreads();

    // ---- energies: lane = t, warp w covers a-pairs [w*16, w*16+16) ----
    const int pbase = w * 16;
    for (int g = 0; g < 4; g++) {
        const float* pmB = pm + ((size_t)b * TT + t0 + g * 32) * DATT;
        for (int i = tid; i < 32 * 128; i += 128) {
            int t = i >> 7, a = i & 127;
            s_pm[t * 129 + a] = pmB[i];
        }
        __syncthreads();

        // duplicated loc pairs, packed once per group
        ull locd[32];
        int tl = g * 32 + lane;
        #pragma unroll
        for (int f = 0; f < 32; f++) {
            float l = s_loc[tl * 33 + f];
            locd[f] = pack2(l, l);
        }

        float epart = 0.f;
        #pragma unroll 2
        for (int pp = 0; pp < 16; pp++) {
            int p = pbase + pp;
            ull acc = ((const ull*)s_pq)[p];               // (pq[2p], pq[2p+1])
            const ulonglong2* wrow = (const ulonglong2*)(s_wd + p * 64);
            #pragma unroll
            for (int j = 0; j < 16; j++) {
                ulonglong2 w2 = wrow[j];                   // LDS.128: f=2j and f=2j+1 pairs
                acc = ffma2u(locd[2 * j],     w2.x, acc);
                acc = ffma2u(locd[2 * j + 1], w2.y, acc);
            }
            float2 a2 = unpack2(acc);
            float x0 = a2.x + s_pm[lane * 129 + 2 * p];
            float x1 = a2.y + s_pm[lane * 129 + 2 * p + 1];
            epart = fmaf(s_wv[2 * p],     tanh_fast(x0), epart);
            epart = fmaf(s_wv[2 * p + 1], tanh_fast(x1), epart);
        }
        s_ep[w * 32 + lane] = epart;
        __syncthreads();
        if (tid < 32) {
            float e = s_ep[tid] + s_ep[32 + tid] + s_ep[64 + tid] + s_ep[96 + tid];
            g_energy[(size_t)b * TT + t0 + g * 32 + tid] = e;
        }
        __syncthreads();
    }
}

// ---------------- K2: masked softmax (mask = int32) ----------------
__global__ __launch_bounds__(256) void softmax_kernel(
    const int* __restrict__ mask, float* __restrict__ out_w)
{
    __shared__ float red[32];
    int tid = threadIdx.x, b = blockIdx.x;
    float vals[8];
    float mx = -CUDART_INF_F;
    #pragma unroll
    for (int j = 0; j < 8; j++) {
        int t = tid + j * 256;
        float e = g_energy[(size_t)b * TT + t];
        float v = (mask[(size_t)b * TT + t] != 0) ? -CUDART_INF_F : e;
        vals[j] = v;
        mx = fmaxf(mx, v);
    }
    #pragma unroll
    for (int off = 16; off; off >>= 1) mx = fmaxf(mx, __shfl_xor_sync(0xffffffffu, mx, off));
    if ((tid & 31) == 0) red[tid >> 5] = mx;
    __syncthreads();
    if (tid < 32) {
        float m = (tid < 8) ? red[tid] : -CUDART_INF_F;
        #pragma unroll
        for (int off = 4; off; off >>= 1) m = fmaxf(m, __shfl_xor_sync(0xffffffffu, m, off));
        red[tid] = m;
    }
    __syncthreads();
    mx = red[0];

    float s = 0.f;
    #pragma unroll
    for (int j = 0; j < 8; j++) { float ev = __expf(vals[j] - mx); vals[j] = ev; s += ev; }
    #pragma unroll
    for (int off = 16; off; off >>= 1) s += __shfl_xor_sync(0xffffffffu, s, off);
    __syncthreads();
    if ((tid & 31) == 0) red[tid >> 5] = s;
    __syncthreads();
    if (tid < 32) {
        float m = (tid < 8) ? red[tid] : 0.f;
        #pragma unroll
        for (int off = 4; off; off >>= 1) m += __shfl_xor_sync(0xffffffffu, m, off);
        red[tid] = m;
    }
    __syncthreads();
    float inv = 1.f / red[0];
    #pragma unroll
    for (int j = 0; j < 8; j++) out_w[(size_t)b * TT + tid + j * 256] = vals[j] * inv;
}

// ---------------- K3: context partials (1024 blocks, MLP=8 batched loads) ----------------
__global__ __launch_bounds__(128) void context_kernel(
    const float* __restrict__ memory, const float* __restrict__ wgt)
{
    __shared__ float s_w[128];
    int tid = threadIdx.x;
    int b = blockIdx.y, ts = blockIdx.x;
    int t0 = ts * 128;
    s_w[tid] = wgt[(size_t)b * TT + t0 + tid];
    __syncthreads();

    const float4* m4 = (const float4*)(memory + ((size_t)b * TT + t0) * DEMB) + tid;
    float4 acc = make_float4(0.f, 0.f, 0.f, 0.f);
    for (int i = 0; i < 128; i += 8) {
        float4 v[8];
        #pragma unroll
        for (int u = 0; u < 8; u++) v[u] = m4[(size_t)(i + u) * 128];
        #pragma unroll
        for (int u = 0; u < 8; u++) {
            float w = s_w[i + u];
            acc.x = fmaf(w, v[u].x, acc.x);
            acc.y = fmaf(w, v[u].y, acc.y);
            acc.z = fmaf(w, v[u].z, acc.z);
            acc.w = fmaf(w, v[u].w, acc.w);
        }
    }
    ((float4*)g_ctx_part)[(size_t)ts * (BB * DEMB / 4) + b * (DEMB / 4) + tid] = acc;
}

// ---------------- K4: reduce context partials ----------------
__global__ __launch_bounds__(256) void reduce_kernel(float* __restrict__ out_ctx)
{
    int i = blockIdx.x * 256 + threadIdx.x;
    float s = 0.f;
    #pragma unroll
    for (int ts = 0; ts < NSPLIT; ts++) s += g_ctx_part[(size_t)ts * BB * DEMB + i];
    out_ctx[i] = s;
}

// ---------------- launch ----------------
extern "C" void kernel_launch(void* const* d_in, const int* in_sizes, int n_in,
                              void* d_out, int out_size)
{
    const float* hidden = (const float*)d_in[0];
    const float* memory = (const float*)d_in[1];
    const float* pm     = (const float*)d_in[2];
    const float* awc    = (const float*)d_in[3];
    const int*   mask   = (const int*)d_in[4];
    const float* Wq     = (const float*)d_in[5];
    const float* Wv     = (const float*)d_in[6];
    const float* convw  = (const float*)d_in[7];
    const float* Wd     = (const float*)d_in[8];

    float* out     = (float*)d_out;
    float* out_ctx = out;                  // [B, 512]
    float* out_w   = out + BB * DEMB;      // [B, T]

    cudaFuncSetAttribute(energy_kernel,
                         cudaFuncAttributeMaxDynamicSharedMemorySize, K1_SMEM_BYTES);

    prep_kernel<<<64, 128>>>(hidden, Wq, convw, Wd);
    energy_kernel<<<dim3(16, 64), 128, K1_SMEM_BYTES>>>(pm, awc, Wv);
    softmax_kernel<<<64, 256>>>(mask, out_w);
    context_kernel<<<dim3(NSPLIT, 64), 128>>>(memory, out_w);
    reduce_kernel<<<128, 256>>>(out_ctx);
}

// round 4
// speedup vs baseline: 1.3833x; 1.3013x over previous
#include <cuda_runtime.h>
#include <cuda_bf16.h>
#include <math_constants.h>
#include <cstdint>

#define BB    64
#define TT    2048
#define DRNN  1024
#define DEMB  512
#define DATT  128
#define NF    32
#define KS    31
#define PADW  15
#define NSPLIT 32

// ---------------- device scratch ----------------
__device__ float  g_pq[BB * DATT];
__device__ float2 g_cw2[62 * 16];            // [ck][fp] = (cw[2fp][ck], cw[2fp+1][ck])
__device__ float  g_energy[BB * TT];
__device__ float  g_ctx_part[NSPLIT * BB * DEMB];

typedef unsigned long long ull;

// ---------------- helpers: zero-mov f32x2 ----------------
__device__ __forceinline__ ull ffma2u(ull a, ull b, ull c) {
    ull d;
    asm("fma.rn.f32x2 %0, %1, %2, %3;" : "=l"(d) : "l"(a), "l"(b), "l"(c));
    return d;
}
__device__ __forceinline__ ull add2u(ull a, ull b) {
    ull d;
    asm("add.rn.f32x2 %0, %1, %2;" : "=l"(d) : "l"(a), "l"(b));
    return d;
}
__device__ __forceinline__ ull pack2(float x, float y) {
    ull r; asm("mov.b64 %0, {%1, %2};" : "=l"(r) : "f"(x), "f"(y)); return r;
}
__device__ __forceinline__ float2 unpack2(ull v) {
    float2 f; asm("mov.b64 {%0, %1}, %2;" : "=f"(f.x), "=f"(f.y) : "l"(v)); return f;
}
__device__ __forceinline__ float tanh_fast(float x) {
    float y; asm("tanh.approx.f32 %0, %1;" : "=f"(y) : "f"(x)); return y;
}

// ---------------- K0: pq GEMM + conv weight repacking ----------------
__global__ __launch_bounds__(128) void prep_kernel(
    const float* __restrict__ hidden, const float* __restrict__ Wq,
    const float* __restrict__ convw)
{
    __shared__ float s_h[DRNN];
    int tid = threadIdx.x, b = blockIdx.x;
    for (int i = tid; i < DRNN; i += 128) s_h[i] = hidden[(size_t)b * DRNN + i];
    __syncthreads();

    int w = tid >> 5, lane = tid & 31;
    for (int a = w; a < DATT; a += 4) {
        const float* wq = Wq + (size_t)a * DRNN;
        float acc = 0.f;
        #pragma unroll 8
        for (int k = lane; k < DRNN; k += 32) acc = fmaf(s_h[k], wq[k], acc);
        #pragma unroll
        for (int off = 16; off; off >>= 1) acc += __shfl_down_sync(0xffffffffu, acc, off);
        if (lane == 0) g_pq[b * DATT + a] = acc;
    }

    if (b == 0) {
        for (int i = tid; i < 62 * 16; i += 128) {
            int ck = i >> 4, fp = i & 15;
            g_cw2[i] = make_float2(convw[(2 * fp) * 62 + ck], convw[(2 * fp + 1) * 62 + ck]);
        }
    }
}

// ---------------- dummy kernels (shift ncu capture slot onto energy) ----------------
__global__ void dummy_kernel() {}

// ---------------- K1: conv + paw + tanh + v-dot -> energies ----------------
// 128 threads = 4 warps; block covers 128 t's; thread tid owns a = tid.
// Wd row in registers (16 f-pairs); loc broadcast from smem; pm direct coalesced LDG.
#define LOCS 36   // s_loc row stride in floats (16B-aligned rows)

__global__ __launch_bounds__(128) void energy_kernel(
    const float* __restrict__ pm, const float* __restrict__ aw,
    const float* __restrict__ wv, const float* __restrict__ Wd)
{
    __shared__ float s_aw[2 * 160];
    __shared__ float s_cw[62 * 32];
    __shared__ float s_loc[128 * LOCS];
    __shared__ float s_red[4 * 128];

    int tid = threadIdx.x;
    int b   = blockIdx.y;
    int t0  = blockIdx.x * 128;
    int w   = tid >> 5, lane = tid & 31;
    const int a = tid;

    // ---- stage conv inputs ----
    const float* awB = aw + (size_t)b * 2 * TT;
    for (int i = tid; i < 2 * 158; i += 128) {
        int c = i / 158, j = i - c * 158;
        int tg = t0 + j - PADW;
        s_aw[c * 160 + j] = (tg >= 0 && tg < TT) ? awB[(size_t)c * TT + tg] : 0.f;
    }
    {
        const float4* src = (const float4*)g_cw2;   // 496 float4
        float4* dst = (float4*)s_cw;
        for (int i = tid; i < 496; i += 128) dst[i] = src[i];
    }
    __syncthreads();

    // ---- conv: thread tid -> loc[t0+tid][all 32 f] ----
    {
        ull acc[16];
        #pragma unroll
        for (int fp = 0; fp < 16; fp++) acc[fp] = 0ULL;
        #pragma unroll 2
        for (int ck = 0; ck < 62; ck++) {
            int c = (ck >= 31), k = ck - c * 31;
            float av = s_aw[c * 160 + tid + k];
            ull av2 = pack2(av, av);
            const ulonglong2* row = (const ulonglong2*)(s_cw + ck * 32);
            #pragma unroll
            for (int q = 0; q < 8; q++) {
                ulonglong2 w2 = row[q];
                acc[2 * q]     = ffma2u(av2, w2.x, acc[2 * q]);
                acc[2 * q + 1] = ffma2u(av2, w2.y, acc[2 * q + 1]);
            }
        }
        #pragma unroll
        for (int fp = 0; fp < 16; fp++) {
            float2 a2 = unpack2(acc[fp]);
            *(float2*)(s_loc + tid * LOCS + 2 * fp) = a2;   // s_loc[t][f]
        }
    }
    __syncthreads();

    // ---- per-thread params (loaded after conv to limit register peak) ----
    float pq_a = g_pq[b * DATT + a];
    float wv_a = wv[a];
    ulonglong2 wd[8];                                       // 16 f-pairs of Wd[a][*]
    {
        const ulonglong2* wrow = (const ulonglong2*)(Wd + (size_t)a * NF);
        #pragma unroll
        for (int q = 0; q < 8; q++) wd[q] = wrow[q];
    }

    // ---- main loop over t (batch 4 for ILP / MLP) ----
    const float* pmB = pm + ((size_t)b * TT + t0) * DATT + a;
    for (int tb = 0; tb < 128; tb += 4) {
        float pmv[4];
        #pragma unroll
        for (int u = 0; u < 4; u++) pmv[u] = pmB[(size_t)(tb + u) * DATT];

        float c[4];
        #pragma unroll
        for (int u = 0; u < 4; u++) {
            const float* lrow = s_loc + (tb + u) * LOCS;
            ull acc0 = 0ULL, acc1 = 0ULL;
            #pragma unroll
            for (int q = 0; q < 8; q++) {
                ulonglong2 l = *(const ulonglong2*)(lrow + 4 * q);  // broadcast LDS.128
                acc0 = ffma2u(l.x, wd[q].x, acc0);
                acc1 = ffma2u(l.y, wd[q].y, acc1);
            }
            float2 a2 = unpack2(add2u(acc0, acc1));
            float x = pq_a + pmv[u] + (a2.x + a2.y);
            c[u] = wv_a * tanh_fast(x);
        }
        #pragma unroll
        for (int u = 0; u < 4; u++) {
            float r = c[u];
            #pragma unroll
            for (int off = 16; off; off >>= 1) r += __shfl_xor_sync(0xffffffffu, r, off);
            if (lane == 0) s_red[w * 128 + tb + u] = r;
        }
    }
    __syncthreads();

    // ---- combine 4 warp partials per t ----
    float e = s_red[tid] + s_red[128 + tid] + s_red[256 + tid] + s_red[384 + tid];
    g_energy[(size_t)b * TT + t0 + tid] = e;
}

// ---------------- K2: masked softmax (mask = int32) ----------------
__global__ __launch_bounds__(256) void softmax_kernel(
    const int* __restrict__ mask, float* __restrict__ out_w)
{
    __shared__ float red[32];
    int tid = threadIdx.x, b = blockIdx.x;
    float vals[8];
    float mx = -CUDART_INF_F;
    #pragma unroll
    for (int j = 0; j < 8; j++) {
        int t = tid + j * 256;
        float e = g_energy[(size_t)b * TT + t];
        float v = (mask[(size_t)b * TT + t] != 0) ? -CUDART_INF_F : e;
        vals[j] = v;
        mx = fmaxf(mx, v);
    }
    #pragma unroll
    for (int off = 16; off; off >>= 1) mx = fmaxf(mx, __shfl_xor_sync(0xffffffffu, mx, off));
    if ((tid & 31) == 0) red[tid >> 5] = mx;
    __syncthreads();
    if (tid < 32) {
        float m = (tid < 8) ? red[tid] : -CUDART_INF_F;
        #pragma unroll
        for (int off = 4; off; off >>= 1) m = fmaxf(m, __shfl_xor_sync(0xffffffffu, m, off));
        red[tid] = m;
    }
    __syncthreads();
    mx = red[0];

    float s = 0.f;
    #pragma unroll
    for (int j = 0; j < 8; j++) { float ev = __expf(vals[j] - mx); vals[j] = ev; s += ev; }
    #pragma unroll
    for (int off = 16; off; off >>= 1) s += __shfl_xor_sync(0xffffffffu, s, off);
    __syncthreads();
    if ((tid & 31) == 0) red[tid >> 5] = s;
    __syncthreads();
    if (tid < 32) {
        float m = (tid < 8) ? red[tid] : 0.f;
        #pragma unroll
        for (int off = 4; off; off >>= 1) m += __shfl_xor_sync(0xffffffffu, m, off);
        red[tid] = m;
    }
    __syncthreads();
    float inv = 1.f / red[0];
    #pragma unroll
    for (int j = 0; j < 8; j++) out_w[(size_t)b * TT + tid + j * 256] = vals[j] * inv;
}

// ---------------- K3: context partials (2048 blocks, MLP=8 batched loads) ----------------
__global__ __launch_bounds__(128) void context_kernel(
    const float* __restrict__ memory, const float* __restrict__ wgt)
{
    __shared__ float s_w[64];
    int tid = threadIdx.x;
    int b = blockIdx.y, ts = blockIdx.x;
    int t0 = ts * 64;
    if (tid < 64) s_w[tid] = wgt[(size_t)b * TT + t0 + tid];
    __syncthreads();

    const float4* m4 = (const float4*)(memory + ((size_t)b * TT + t0) * DEMB) + tid;
    float4 acc = make_float4(0.f, 0.f, 0.f, 0.f);
    for (int i = 0; i < 64; i += 8) {
        float4 v[8];
        #pragma unroll
        for (int u = 0; u < 8; u++) v[u] = m4[(size_t)(i + u) * 128];
        #pragma unroll
        for (int u = 0; u < 8; u++) {
            float w = s_w[i + u];
            acc.x = fmaf(w, v[u].x, acc.x);
            acc.y = fmaf(w, v[u].y, acc.y);
            acc.z = fmaf(w, v[u].z, acc.z);
            acc.w = fmaf(w, v[u].w, acc.w);
        }
    }
    ((float4*)g_ctx_part)[(size_t)ts * (BB * DEMB / 4) + b * (DEMB / 4) + tid] = acc;
}

// ---------------- K4: reduce context partials ----------------
__global__ __launch_bounds__(256) void reduce_kernel(float* __restrict__ out_ctx)
{
    int i = blockIdx.x * 256 + threadIdx.x;
    float s = 0.f;
    #pragma unroll
    for (int ts = 0; ts < NSPLIT; ts++) s += g_ctx_part[(size_t)ts * BB * DEMB + i];
    out_ctx[i] = s;
}

// ---------------- launch ----------------
extern "C" void kernel_launch(void* const* d_in, const int* in_sizes, int n_in,
                              void* d_out, int out_size)
{
    const float* hidden = (const float*)d_in[0];
    const float* memory = (const float*)d_in[1];
    const float* pm     = (const float*)d_in[2];
    const float* awc    = (const float*)d_in[3];
    const int*   mask   = (const int*)d_in[4];
    const float* Wq     = (const float*)d_in[5];
    const float* Wv     = (const float*)d_in[6];
    const float* convw  = (const float*)d_in[7];
    const float* Wd     = (const float*)d_in[8];

    float* out     = (float*)d_out;
    float* out_ctx = out;                  // [B, 512]
    float* out_w   = out + BB * DEMB;      // [B, T]

    prep_kernel<<<64, 128>>>(hidden, Wq, convw);
    dummy_kernel<<<1, 32>>>();             // shift ncu capture slot
    dummy_kernel<<<1, 32>>>();             // so energy_kernel lands on it
    energy_kernel<<<dim3(16, 64), 128>>>(pm, awc, Wv, Wd);
    softmax_kernel<<<64, 256>>>(mask, out_w);
    context_kernel<<<dim3(NSPLIT, 64), 128>>>(memory, out_w);
    reduce_kernel<<<128, 256>>>(out_ctx);
}

// round 5
// speedup vs baseline: 1.7460x; 1.2622x over previous
#include <cuda_runtime.h>
#include <cuda_bf16.h>
#include <math_constants.h>
#include <cstdint>

#define BB    64
#define TT    2048
#define DRNN  1024
#define DEMB  512
#define DATT  128
#define NF    32
#define KS    31
#define PADW  15
#define NSPLIT 32
#define LOCS  36    // s_loc row stride (floats); 144 B, 16B-aligned

// ---------------- device scratch ----------------
__device__ float  g_pq[BB * DATT];
__device__ float2 g_cw2[62 * 16];
__device__ float  g_energy[BB * TT];
__device__ float  g_ctx_part[NSPLIT * BB * DEMB];

typedef unsigned long long ull;

// ---------------- helpers: zero-mov f32x2 ----------------
__device__ __forceinline__ ull ffma2u(ull a, ull b, ull c) {
    ull d;
    asm("fma.rn.f32x2 %0, %1, %2, %3;" : "=l"(d) : "l"(a), "l"(b), "l"(c));
    return d;
}
__device__ __forceinline__ ull add2u(ull a, ull b) {
    ull d;
    asm("add.rn.f32x2 %0, %1, %2;" : "=l"(d) : "l"(a), "l"(b));
    return d;
}
__device__ __forceinline__ ull pack2(float x, float y) {
    ull r; asm("mov.b64 %0, {%1, %2};" : "=l"(r) : "f"(x), "f"(y)); return r;
}
__device__ __forceinline__ float2 unpack2(ull v) {
    float2 f; asm("mov.b64 {%0, %1}, %2;" : "=f"(f.x), "=f"(f.y) : "l"(v)); return f;
}
__device__ __forceinline__ float tanh_fast(float x) {
    float y; asm("tanh.approx.f32 %0, %1;" : "=f"(y) : "f"(x)); return y;
}

// ---------------- K0: pq GEMM (4x parallel) + conv weight repacking ----------------
__global__ __launch_bounds__(128) void prep_kernel(
    const float* __restrict__ hidden, const float* __restrict__ Wq,
    const float* __restrict__ convw)
{
    __shared__ float s_h[DRNN];
    int tid = threadIdx.x, b = blockIdx.x, slice = blockIdx.y;
    for (int i = tid; i < DRNN; i += 128) s_h[i] = hidden[(size_t)b * DRNN + i];
    __syncthreads();

    int w = tid >> 5, lane = tid & 31;
    #pragma unroll
    for (int i = 0; i < 8; i++) {
        int a = slice * 32 + w * 8 + i;
        const float* wq = Wq + (size_t)a * DRNN;
        float acc0 = 0.f, acc1 = 0.f;
        #pragma unroll 4
        for (int k = lane; k < DRNN; k += 64) {
            acc0 = fmaf(s_h[k],      wq[k],      acc0);
            acc1 = fmaf(s_h[k + 32], wq[k + 32], acc1);
        }
        float acc = acc0 + acc1;
        #pragma unroll
        for (int off = 16; off; off >>= 1) acc += __shfl_down_sync(0xffffffffu, acc, off);
        if (lane == 0) g_pq[b * DATT + a] = acc;
    }

    if (b == 0 && slice == 0) {
        for (int i = tid; i < 62 * 16; i += 128) {
            int ck = i >> 4, fp = i & 15;
            g_cw2[i] = make_float2(convw[(2 * fp) * 62 + ck], convw[(2 * fp + 1) * 62 + ck]);
        }
    }
}

// ---------------- dummy kernels (keep ncu capture slot on energy) ----------------
__global__ void dummy_kernel() {}

// ---------------- K1: conv + paw + tanh + v-dot -> energies ----------------
// 128 threads = 4 warps. Warp w = (ti = w>>1 : t-half of 64, aj = w&1 : a-half of 64).
// Thread owns a-pair a0 = aj*64 + 2*lane; both Wd rows (64 floats) in registers.
__global__ __launch_bounds__(128) void energy_kernel(
    const float* __restrict__ pm, const float* __restrict__ aw,
    const float* __restrict__ wv, const float* __restrict__ Wd)
{
    __shared__ __align__(16) float s_aw[2 * 160];
    __shared__ __align__(16) float s_cw[62 * 32];
    __shared__ __align__(16) float s_loc[128 * LOCS];
    __shared__ float s_red[128 * 2];

    int tid = threadIdx.x;
    int b   = blockIdx.y;
    int t0  = blockIdx.x * 128;
    int w   = tid >> 5, lane = tid & 31;

    // ---- stage conv inputs ----
    const float* awB = aw + (size_t)b * 2 * TT;
    for (int i = tid; i < 2 * 158; i += 128) {
        int c = i / 158, j = i - c * 158;
        int tg = t0 + j - PADW;
        s_aw[c * 160 + j] = (tg >= 0 && tg < TT) ? awB[(size_t)c * TT + tg] : 0.f;
    }
    {
        const float4* src = (const float4*)g_cw2;
        float4* dst = (float4*)s_cw;
        for (int i = tid; i < 496; i += 128) dst[i] = src[i];
    }
    __syncthreads();

    // ---- conv: thread tid -> loc[t0+tid][all 32 f] ----
    {
        ull acc[16];
        #pragma unroll
        for (int fp = 0; fp < 16; fp++) acc[fp] = 0ULL;
        #pragma unroll 2
        for (int ck = 0; ck < 62; ck++) {
            int c = (ck >= 31), k = ck - c * 31;
            float av = s_aw[c * 160 + tid + k];
            ull av2 = pack2(av, av);
            const ulonglong2* row = (const ulonglong2*)(s_cw + ck * 32);
            #pragma unroll
            for (int q = 0; q < 8; q++) {
                ulonglong2 w2 = row[q];
                acc[2 * q]     = ffma2u(av2, w2.x, acc[2 * q]);
                acc[2 * q + 1] = ffma2u(av2, w2.y, acc[2 * q + 1]);
            }
        }
        #pragma unroll
        for (int fp = 0; fp < 16; fp++) {
            float2 a2 = unpack2(acc[fp]);
            *(float2*)(s_loc + tid * LOCS + 2 * fp) = a2;
        }
    }
    __syncthreads();

    // ---- per-thread params ----
    const int ti = w >> 1, aj = w & 1;
    const int a0 = aj * 64 + 2 * lane;
    float2 pq2 = *(const float2*)(g_pq + b * DATT + a0);
    float2 wv2 = *(const float2*)(wv + a0);
    ull wp[32];                                   // Wd rows a0, a0+1: 64 floats
    {
        const ull* src = (const ull*)(Wd + (size_t)a0 * NF);
        #pragma unroll
        for (int i = 0; i < 32; i++) wp[i] = src[i];
    }

    // ---- main loop over warp's 64 t's (2 per iteration) ----
    const float* pmB = pm + ((size_t)b * TT + t0 + ti * 64) * DATT + a0;
    const float* locBase = s_loc + ti * 64 * LOCS;
    float2 pmv0 = *(const float2*)(pmB);
    float2 pmv1 = *(const float2*)(pmB + DATT);

    for (int tl = 0; tl < 64; tl += 2) {
        float2 cur0 = pmv0, cur1 = pmv1;
        if (tl + 2 < 64) {                        // prefetch next pair
            pmv0 = *(const float2*)(pmB + (size_t)(tl + 2) * DATT);
            pmv1 = *(const float2*)(pmB + (size_t)(tl + 3) * DATT);
        }

        float c[2];
        #pragma unroll
        for (int u = 0; u < 2; u++) {
            const ulonglong2* lrow = (const ulonglong2*)(locBase + (tl + u) * LOCS);
            ull a0c = 0ULL, a1c = 0ULL, b0c = 0ULL, b1c = 0ULL;
            #pragma unroll
            for (int q = 0; q < 8; q++) {
                ulonglong2 l = lrow[q];           // loc f = 4q..4q+3 (2 pairs)
                a0c = ffma2u(l.x, wp[2 * q],          a0c);
                a1c = ffma2u(l.y, wp[2 * q + 1],      a1c);
                b0c = ffma2u(l.x, wp[16 + 2 * q],     b0c);
                b1c = ffma2u(l.y, wp[16 + 2 * q + 1], b1c);
            }
            float2 pa = unpack2(add2u(a0c, a1c));
            float2 pb = unpack2(add2u(b0c, b1c));
            float2 pmu = u ? cur1 : cur0;
            float x0 = pq2.x + pmu.x + (pa.x + pa.y);
            float x1 = pq2.y + pmu.y + (pb.x + pb.y);
            c[u] = fmaf(wv2.x, tanh_fast(x0), wv2.y * tanh_fast(x1));
        }
        // two interleaved 5-level butterflies
        #pragma unroll
        for (int off = 16; off; off >>= 1) {
            c[0] += __shfl_xor_sync(0xffffffffu, c[0], off);
            c[1] += __shfl_xor_sync(0xffffffffu, c[1], off);
        }
        if (lane == 0) {
            s_red[(ti * 64 + tl) * 2 + aj]     = c[0];
            s_red[(ti * 64 + tl + 1) * 2 + aj] = c[1];
        }
    }
    __syncthreads();

    float e = s_red[tid * 2] + s_red[tid * 2 + 1];
    g_energy[(size_t)b * TT + t0 + tid] = e;
}

// ---------------- K2: masked softmax (mask = int32) ----------------
__global__ __launch_bounds__(256) void softmax_kernel(
    const int* __restrict__ mask, float* __restrict__ out_w)
{
    __shared__ float red[32];
    int tid = threadIdx.x, b = blockIdx.x;
    float vals[8];
    float mx = -CUDART_INF_F;
    #pragma unroll
    for (int j = 0; j < 8; j++) {
        int t = tid + j * 256;
        float e = g_energy[(size_t)b * TT + t];
        float v = (mask[(size_t)b * TT + t] != 0) ? -CUDART_INF_F : e;
        vals[j] = v;
        mx = fmaxf(mx, v);
    }
    #pragma unroll
    for (int off = 16; off; off >>= 1) mx = fmaxf(mx, __shfl_xor_sync(0xffffffffu, mx, off));
    if ((tid & 31) == 0) red[tid >> 5] = mx;
    __syncthreads();
    if (tid < 32) {
        float m = (tid < 8) ? red[tid] : -CUDART_INF_F;
        #pragma unroll
        for (int off = 4; off; off >>= 1) m = fmaxf(m, __shfl_xor_sync(0xffffffffu, m, off));
        red[tid] = m;
    }
    __syncthreads();
    mx = red[0];

    float s = 0.f;
    #pragma unroll
    for (int j = 0; j < 8; j++) { float ev = __expf(vals[j] - mx); vals[j] = ev; s += ev; }
    #pragma unroll
    for (int off = 16; off; off >>= 1) s += __shfl_xor_sync(0xffffffffu, s, off);
    __syncthreads();
    if ((tid & 31) == 0) red[tid >> 5] = s;
    __syncthreads();
    if (tid < 32) {
        float m = (tid < 8) ? red[tid] : 0.f;
        #pragma unroll
        for (int off = 4; off; off >>= 1) m += __shfl_xor_sync(0xffffffffu, m, off);
        red[tid] = m;
    }
    __syncthreads();
    float inv = 1.f / red[0];
    #pragma unroll
    for (int j = 0; j < 8; j++) out_w[(size_t)b * TT + tid + j * 256] = vals[j] * inv;
}

// ---------------- K3: context partials ----------------
__global__ __launch_bounds__(128) void context_kernel(
    const float* __restrict__ memory, const float* __restrict__ wgt)
{
    __shared__ float s_w[64];
    int tid = threadIdx.x;
    int b = blockIdx.y, ts = blockIdx.x;
    int t0 = ts * 64;
    if (tid < 64) s_w[tid] = wgt[(size_t)b * TT + t0 + tid];
    __syncthreads();

    const float4* m4 = (const float4*)(memory + ((size_t)b * TT + t0) * DEMB) + tid;
    float4 acc = make_float4(0.f, 0.f, 0.f, 0.f);
    for (int i = 0; i < 64; i += 8) {
        float4 v[8];
        #pragma unroll
        for (int u = 0; u < 8; u++) v[u] = m4[(size_t)(i + u) * 128];
        #pragma unroll
        for (int u = 0; u < 8; u++) {
            float w = s_w[i + u];
            acc.x = fmaf(w, v[u].x, acc.x);
            acc.y = fmaf(w, v[u].y, acc.y);
            acc.z = fmaf(w, v[u].z, acc.z);
            acc.w = fmaf(w, v[u].w, acc.w);
        }
    }
    ((float4*)g_ctx_part)[(size_t)ts * (BB * DEMB / 4) + b * (DEMB / 4) + tid] = acc;
}

// ---------------- K4: reduce context partials ----------------
__global__ __launch_bounds__(256) void reduce_kernel(float* __restrict__ out_ctx)
{
    int i = blockIdx.x * 256 + threadIdx.x;
    float s = 0.f;
    #pragma unroll
    for (int ts = 0; ts < NSPLIT; ts++) s += g_ctx_part[(size_t)ts * BB * DEMB + i];
    out_ctx[i] = s;
}

// ---------------- launch ----------------
extern "C" void kernel_launch(void* const* d_in, const int* in_sizes, int n_in,
                              void* d_out, int out_size)
{
    const float* hidden = (const float*)d_in[0];
    const float* memory = (const float*)d_in[1];
    const float* pm     = (const float*)d_in[2];
    const float* awc    = (const float*)d_in[3];
    const int*   mask   = (const int*)d_in[4];
    const float* Wq     = (const float*)d_in[5];
    const float* Wv     = (const float*)d_in[6];
    const float* convw  = (const float*)d_in[7];
    const float* Wd     = (const float*)d_in[8];

    float* out     = (float*)d_out;
    float* out_ctx = out;                  // [B, 512]
    float* out_w   = out + BB * DEMB;      // [B, T]

    prep_kernel<<<dim3(64, 4), 128>>>(hidden, Wq, convw);
    dummy_kernel<<<1, 32>>>();
    dummy_kernel<<<1, 32>>>();
    energy_kernel<<<dim3(16, 64), 128>>>(pm, awc, Wv, Wd);
    softmax_kernel<<<64, 256>>>(mask, out_w);
    context_kernel<<<dim3(NSPLIT, 64), 128>>>(memory, out_w);
    reduce_kernel<<<128, 256>>>(out_ctx);
}

// round 6
// speedup vs baseline: 1.7818x; 1.0205x over previous
#include <cuda_runtime.h>
#include <cuda_bf16.h>
#include <math_constants.h>
#include <cstdint>

#define BB    64
#define TT    2048
#define DRNN  1024
#define DEMB  512
#define DATT  128
#define NF    32
#define KS    31
#define PADW  15
#define NSPLIT 32
#define LOCS  36
#define PMSTRIDE 132            // floats per staged pm row
#define STAGE_FLOATS (8 * PMSTRIDE)

// ---------------- device scratch ----------------
__device__ float  g_pq[BB * DATT];
__device__ float2 g_cw2[62 * 16];
__device__ float  g_energy[BB * TT];
__device__ float  g_ctx_part[NSPLIT * BB * DEMB];

typedef unsigned long long ull;

// ---------------- helpers ----------------
__device__ __forceinline__ ull ffma2u(ull a, ull b, ull c) {
    ull d;
    asm("fma.rn.f32x2 %0, %1, %2, %3;" : "=l"(d) : "l"(a), "l"(b), "l"(c));
    return d;
}
__device__ __forceinline__ ull add2u(ull a, ull b) {
    ull d;
    asm("add.rn.f32x2 %0, %1, %2;" : "=l"(d) : "l"(a), "l"(b));
    return d;
}
__device__ __forceinline__ ull pack2(float x, float y) {
    ull r; asm("mov.b64 %0, {%1, %2};" : "=l"(r) : "f"(x), "f"(y)); return r;
}
__device__ __forceinline__ float2 unpack2(ull v) {
    float2 f; asm("mov.b64 {%0, %1}, %2;" : "=f"(f.x), "=f"(f.y) : "l"(v)); return f;
}
__device__ __forceinline__ float tanh_fast(float x) {
    float y; asm("tanh.approx.f32 %0, %1;" : "=f"(y) : "f"(x)); return y;
}
__device__ __forceinline__ void cp_async8(uint32_t dst, const void* src) {
    asm volatile("cp.async.ca.shared.global [%0], [%1], 8;" :: "r"(dst), "l"(src));
}

// ---------------- K0: pq GEMM (4x parallel) + conv weight repacking ----------------
__global__ __launch_bounds__(128) void prep_kernel(
    const float* __restrict__ hidden, const float* __restrict__ Wq,
    const float* __restrict__ convw)
{
    __shared__ float s_h[DRNN];
    int tid = threadIdx.x, b = blockIdx.x, slice = blockIdx.y;
    for (int i = tid; i < DRNN; i += 128) s_h[i] = hidden[(size_t)b * DRNN + i];
    __syncthreads();

    int w = tid >> 5, lane = tid & 31;
    #pragma unroll
    for (int i = 0; i < 8; i++) {
        int a = slice * 32 + w * 8 + i;
        const float* wq = Wq + (size_t)a * DRNN;
        float acc0 = 0.f, acc1 = 0.f;
        #pragma unroll 4
        for (int k = lane; k < DRNN; k += 64) {
            acc0 = fmaf(s_h[k],      wq[k],      acc0);
            acc1 = fmaf(s_h[k + 32], wq[k + 32], acc1);
        }
        float acc = acc0 + acc1;
        #pragma unroll
        for (int off = 16; off; off >>= 1) acc += __shfl_down_sync(0xffffffffu, acc, off);
        if (lane == 0) g_pq[b * DATT + a] = acc;
    }

    if (b == 0 && slice == 0) {
        for (int i = tid; i < 62 * 16; i += 128) {
            int ck = i >> 4, fp = i & 15;
            g_cw2[i] = make_float2(convw[(2 * fp) * 62 + ck], convw[(2 * fp + 1) * 62 + ck]);
        }
    }
}

__global__ void dummy_kernel() {}

// ---------------- K1: conv + paw + tanh + v-dot -> energies ----------------
// 4 warps: warp w = (ti = w>>1 t-half, aj = w&1 a-half). Thread owns a-pair a0 = aj*64+2*lane.
// pm staged through smem via cp.async: 8 stages of 8 t per half, ring of 2 buffers,
// 2 stages always in flight; prologue issued before conv so conv hides initial latency.
__global__ __launch_bounds__(128) void energy_kernel(
    const float* __restrict__ pm, const float* __restrict__ aw,
    const float* __restrict__ wv, const float* __restrict__ Wd)
{
    __shared__ __align__(16) float s_aw[2 * 160];
    __shared__ __align__(16) float s_cw[62 * 32];
    __shared__ __align__(16) float s_loc[128 * LOCS];
    __shared__ float s_red[128 * 2];
    __shared__ __align__(16) float s_pm[2][2][STAGE_FLOATS];   // [half][buf][t*132+a]

    int tid = threadIdx.x;
    int b   = blockIdx.y;
    int t0  = blockIdx.x * 128;
    int w   = tid >> 5, lane = tid & 31;
    const int ti = w >> 1, aj = w & 1;
    const int a0 = aj * 64 + 2 * lane;

    // ---- pm pipeline setup + prologue (before conv: conv hides the latency) ----
    const float* pmB = pm + ((size_t)b * TT + t0 + ti * 64) * DATT + a0;
    uint32_t pmS = (uint32_t)__cvta_generic_to_shared(&s_pm[ti][0][0]) + a0 * 4;

    #define ISSUE_STAGE(sg) do {                                              \
        uint32_t dstb = pmS + (((sg) & 1) ? (STAGE_FLOATS * 4) : 0);          \
        const float* srcb = pmB + (size_t)(sg) * 8 * DATT;                    \
        _Pragma("unroll")                                                     \
        for (int t_ = 0; t_ < 8; t_++)                                        \
            cp_async8(dstb + t_ * (PMSTRIDE * 4), srcb + (size_t)t_ * DATT);  \
        asm volatile("cp.async.commit_group;" ::: "memory");                  \
    } while (0)

    ISSUE_STAGE(0);
    ISSUE_STAGE(1);

    // ---- stage conv inputs ----
    const float* awB = aw + (size_t)b * 2 * TT;
    for (int i = tid; i < 2 * 158; i += 128) {
        int c = i / 158, j = i - c * 158;
        int tg = t0 + j - PADW;
        s_aw[c * 160 + j] = (tg >= 0 && tg < TT) ? awB[(size_t)c * TT + tg] : 0.f;
    }
    {
        const float4* src = (const float4*)g_cw2;
        float4* dst = (float4*)s_cw;
        for (int i = tid; i < 496; i += 128) dst[i] = src[i];
    }
    __syncthreads();

    // ---- conv: thread tid -> loc[t0+tid][all 32 f] ----
    {
        ull acc[16];
        #pragma unroll
        for (int fp = 0; fp < 16; fp++) acc[fp] = 0ULL;
        #pragma unroll 2
        for (int ck = 0; ck < 62; ck++) {
            int c = (ck >= 31), k = ck - c * 31;
            float av = s_aw[c * 160 + tid + k];
            ull av2 = pack2(av, av);
            const ulonglong2* row = (const ulonglong2*)(s_cw + ck * 32);
            #pragma unroll
            for (int q = 0; q < 8; q++) {
                ulonglong2 w2 = row[q];
                acc[2 * q]     = ffma2u(av2, w2.x, acc[2 * q]);
                acc[2 * q + 1] = ffma2u(av2, w2.y, acc[2 * q + 1]);
            }
        }
        #pragma unroll
        for (int fp = 0; fp < 16; fp++) {
            float2 a2 = unpack2(acc[fp]);
            *(float2*)(s_loc + tid * LOCS + 2 * fp) = a2;
        }
    }
    __syncthreads();

    // ---- per-thread params ----
    float2 pq2 = *(const float2*)(g_pq + b * DATT + a0);
    float2 wv2 = *(const float2*)(wv + a0);
    ull wp[32];                                   // Wd rows a0, a0+1
    {
        const ull* src = (const ull*)(Wd + (size_t)a0 * NF);
        #pragma unroll
        for (int i = 0; i < 32; i++) wp[i] = src[i];
    }

    // ---- main loop: 8 stages of 8 t ----
    for (int sg = 0; sg < 8; sg++) {
        asm volatile("cp.async.wait_group 1;" ::: "memory");
        const float* pbuf  = &s_pm[ti][sg & 1][0];
        const float* lrowB = s_loc + (ti * 64 + sg * 8) * LOCS;

        #pragma unroll
        for (int tl = 0; tl < 8; tl += 2) {
            float2 cur0 = *(const float2*)(pbuf + tl * PMSTRIDE + a0);
            float2 cur1 = *(const float2*)(pbuf + (tl + 1) * PMSTRIDE + a0);

            float c[2];
            #pragma unroll
            for (int u = 0; u < 2; u++) {
                const ulonglong2* lrow = (const ulonglong2*)(lrowB + (tl + u) * LOCS);
                ull a0c = 0ULL, a1c = 0ULL, b0c = 0ULL, b1c = 0ULL;
                #pragma unroll
                for (int q = 0; q < 8; q++) {
                    ulonglong2 l = lrow[q];
                    a0c = ffma2u(l.x, wp[2 * q],          a0c);
                    a1c = ffma2u(l.y, wp[2 * q + 1],      a1c);
                    b0c = ffma2u(l.x, wp[16 + 2 * q],     b0c);
                    b1c = ffma2u(l.y, wp[16 + 2 * q + 1], b1c);
                }
                float2 pa = unpack2(add2u(a0c, a1c));
                float2 pb = unpack2(add2u(b0c, b1c));
                float2 pmu = u ? cur1 : cur0;
                float x0 = pq2.x + pmu.x + (pa.x + pa.y);
                float x1 = pq2.y + pmu.y + (pb.x + pb.y);
                c[u] = fmaf(wv2.x, tanh_fast(x0), wv2.y * tanh_fast(x1));
            }
            #pragma unroll
            for (int off = 16; off; off >>= 1) {
                c[0] += __shfl_xor_sync(0xffffffffu, c[0], off);
                c[1] += __shfl_xor_sync(0xffffffffu, c[1], off);
            }
            if (lane == 0) {
                int tg = ti * 64 + sg * 8 + tl;
                s_red[tg * 2 + aj]       = c[0];
                s_red[(tg + 1) * 2 + aj] = c[1];
            }
        }
        // refill the buffer just consumed (data-dependence guarantees reads done);
        // empty commit groups keep wait_group 1 correct for the tail stages.
        if (sg < 6) { ISSUE_STAGE(sg + 2); }
        else        { asm volatile("cp.async.commit_group;" ::: "memory"); }
    }
    __syncthreads();

    float e = s_red[tid * 2] + s_red[tid * 2 + 1];
    g_energy[(size_t)b * TT + t0 + tid] = e;
}

// ---------------- K2: masked softmax (mask = int32) ----------------
__global__ __launch_bounds__(256) void softmax_kernel(
    const int* __restrict__ mask, float* __restrict__ out_w)
{
    __shared__ float red[32];
    int tid = threadIdx.x, b = blockIdx.x;
    float vals[8];
    float mx = -CUDART_INF_F;
    #pragma unroll
    for (int j = 0; j < 8; j++) {
        int t = tid + j * 256;
        float e = g_energy[(size_t)b * TT + t];
        float v = (mask[(size_t)b * TT + t] != 0) ? -CUDART_INF_F : e;
        vals[j] = v;
        mx = fmaxf(mx, v);
    }
    #pragma unroll
    for (int off = 16; off; off >>= 1) mx = fmaxf(mx, __shfl_xor_sync(0xffffffffu, mx, off));
    if ((tid & 31) == 0) red[tid >> 5] = mx;
    __syncthreads();
    if (tid < 32) {
        float m = (tid < 8) ? red[tid] : -CUDART_INF_F;
        #pragma unroll
        for (int off = 4; off; off >>= 1) m = fmaxf(m, __shfl_xor_sync(0xffffffffu, m, off));
        red[tid] = m;
    }
    __syncthreads();
    mx = red[0];

    float s = 0.f;
    #pragma unroll
    for (int j = 0; j < 8; j++) { float ev = __expf(vals[j] - mx); vals[j] = ev; s += ev; }
    #pragma unroll
    for (int off = 16; off; off >>= 1) s += __shfl_xor_sync(0xffffffffu, s, off);
    __syncthreads();
    if ((tid & 31) == 0) red[tid >> 5] = s;
    __syncthreads();
    if (tid < 32) {
        float m = (tid < 8) ? red[tid] : 0.f;
        #pragma unroll
        for (int off = 4; off; off >>= 1) m += __shfl_xor_sync(0xffffffffu, m, off);
        red[tid] = m;
    }
    __syncthreads();
    float inv = 1.f / red[0];
    #pragma unroll
    for (int j = 0; j < 8; j++) out_w[(size_t)b * TT + tid + j * 256] = vals[j] * inv;
}

// ---------------- K3: context partials ----------------
__global__ __launch_bounds__(128) void context_kernel(
    const float* __restrict__ memory, const float* __restrict__ wgt)
{
    __shared__ float s_w[64];
    int tid = threadIdx.x;
    int b = blockIdx.y, ts = blockIdx.x;
    int t0 = ts * 64;
    if (tid < 64) s_w[tid] = wgt[(size_t)b * TT + t0 + tid];
    __syncthreads();

    const float4* m4 = (const float4*)(memory + ((size_t)b * TT + t0) * DEMB) + tid;
    float4 acc = make_float4(0.f, 0.f, 0.f, 0.f);
    for (int i = 0; i < 64; i += 8) {
        float4 v[8];
        #pragma unroll
        for (int u = 0; u < 8; u++) v[u] = m4[(size_t)(i + u) * 128];
        #pragma unroll
        for (int u = 0; u < 8; u++) {
            float w = s_w[i + u];
            acc.x = fmaf(w, v[u].x, acc.x);
            acc.y = fmaf(w, v[u].y, acc.y);
            acc.z = fmaf(w, v[u].z, acc.z);
            acc.w = fmaf(w, v[u].w, acc.w);
        }
    }
    ((float4*)g_ctx_part)[(size_t)ts * (BB * DEMB / 4) + b * (DEMB / 4) + tid] = acc;
}

// ---------------- K4: reduce context partials ----------------
__global__ __launch_bounds__(256) void reduce_kernel(float* __restrict__ out_ctx)
{
    int i = blockIdx.x * 256 + threadIdx.x;
    float s = 0.f;
    #pragma unroll
    for (int ts = 0; ts < NSPLIT; ts++) s += g_ctx_part[(size_t)ts * BB * DEMB + i];
    out_ctx[i] = s;
}

// ---------------- launch ----------------
extern "C" void kernel_launch(void* const* d_in, const int* in_sizes, int n_in,
                              void* d_out, int out_size)
{
    const float* hidden = (const float*)d_in[0];
    const float* memory = (const float*)d_in[1];
    const float* pm     = (const float*)d_in[2];
    const float* awc    = (const float*)d_in[3];
    const int*   mask   = (const int*)d_in[4];
    const float* Wq     = (const float*)d_in[5];
    const float* Wv     = (const float*)d_in[6];
    const float* convw  = (const float*)d_in[7];
    const float* Wd     = (const float*)d_in[8];

    float* out     = (float*)d_out;
    float* out_ctx = out;                  // [B, 512]
    float* out_w   = out + BB * DEMB;      // [B, T]

    prep_kernel<<<dim3(64, 4), 128>>>(hidden, Wq, convw);
    dummy_kernel<<<1, 32>>>();
    dummy_kernel<<<1, 32>>>();
    energy_kernel<<<dim3(16, 64), 128>>>(pm, awc, Wv, Wd);
    softmax_kernel<<<64, 256>>>(mask, out_w);
    context_kernel<<<dim3(NSPLIT, 64), 128>>>(memory, out_w);
    reduce_kernel<<<128, 256>>>(out_ctx);
}